// round 10
// baseline (speedup 1.0000x reference)
#include <cuda_runtime.h>
#include <cuda_bf16.h>
#include <math.h>

#define NMAX 100000
#define EMAX 1700000
#define HID 128
#define PROTO 64
#define BN_EPS 1e-5f
#define KC 32

typedef unsigned int uint32;

// ---------------- scratch (device globals: no allocation allowed) ----------------
__device__ float g_h1[NMAX * HID];
__device__ float g_h2[NMAX * HID];
__device__ float g_agg[NMAX * HID];
__device__ float g_p[NMAX * HID];
__device__ float g_p2[NMAX * HID];
__device__ float g_an[NMAX * PROTO];
__device__ int   g_cnt[NMAX];
__device__ int   g_off[NMAX + 1];
__device__ int   g_cur[NMAX];
__device__ int   g_csr[EMAX];
__device__ int   g_total;
__device__ float g_sum[4 * HID];
__device__ float g_sumsq[4 * HID];
__device__ float g_scaleS[4][HID];
__device__ float g_shiftS[4][HID];

// Weights in INTERLEAVED tf32 fragment layout: one float4 per "pair"
//   pair index: ((ktile*16 + ntile)*32 + lane)
//   float4 = { hi(reg0), hi(reg1), lo(reg0), lo(reg1) }
#define WPL(L) ((L) * 8192)
#define WPR(L) (24576 + (L) * 8192)
#define MP0 49152
#define MP1 53248
#define MP2 61440
#define NPAIRS 69632
__device__ float g_wf[NPAIRS * 4];

// ---------------- tf32 + cache-hint helpers ----------------
__device__ __forceinline__ uint32 cvt_tf32(float x) {
    uint32 r;
    asm("cvt.rna.tf32.f32 %0, %1;" : "=r"(r) : "f"(x));
    return r;
}
__device__ __forceinline__ void split_tf32(float x, float& hi, float& lo) {
    uint32 h = cvt_tf32(x);
    hi = __uint_as_float(h);
    lo = __uint_as_float(cvt_tf32(x - hi));
}
__device__ __forceinline__ void mma_tf32(float* c,
                                         uint32 a0, uint32 a1, uint32 a2, uint32 a3,
                                         uint32 b0, uint32 b1) {
    asm volatile("mma.sync.aligned.m16n8k8.row.col.f32.tf32.tf32.f32 "
                 "{%0,%1,%2,%3}, {%4,%5,%6,%7}, {%8,%9}, {%0,%1,%2,%3};"
                 : "+f"(c[0]), "+f"(c[1]), "+f"(c[2]), "+f"(c[3])
                 : "r"(a0), "r"(a1), "r"(a2), "r"(a3), "r"(b0), "r"(b1));
}
// streaming load (don't pollute L1)
__device__ __forceinline__ float4 ldg_ef4(const float* p) {
    float4 v;
    asm("ld.global.nc.L1::evict_first.v4.f32 {%0,%1,%2,%3}, [%4];"
        : "=f"(v.x), "=f"(v.y), "=f"(v.z), "=f"(v.w) : "l"(p));
    return v;
}
// resident load (keep in L1)
__device__ __forceinline__ float4 ldg_el4(const float* p) {
    float4 v;
    asm("ld.global.nc.L1::evict_last.v4.f32 {%0,%1,%2,%3}, [%4];"
        : "=f"(v.x), "=f"(v.y), "=f"(v.z), "=f"(v.w) : "l"(p));
    return v;
}

// ---------------- init ----------------
__global__ void init_kernel() {
    int v = blockIdx.x * blockDim.x + threadIdx.x;
    if (v < 4 * HID) { g_sum[v] = 0.f; g_sumsq[v] = 0.f; }
    if (v == 0) g_total = 0;
}

__global__ void zero_cnt_kernel(int n) {
    int v = blockIdx.x * blockDim.x + threadIdx.x;
    if (v < n) g_cnt[v] = 0;
}
__global__ void count_kernel(const int* __restrict__ tgt, int E) {
    int e = blockIdx.x * blockDim.x + threadIdx.x;
    if (e < E) atomicAdd(&g_cnt[tgt[e]], 1);
}

// ---------------- CSR offset allocation (unordered block bases) ----------------
__global__ void alloc_kernel(int n) {
    __shared__ int wsums[8];
    __shared__ int base_s;
    int tid = threadIdx.x, lane = tid & 31, wid = tid >> 5;
    int i = blockIdx.x * 256 + tid;
    int v = (i < n) ? g_cnt[i] : 0;
    int s = v;
#pragma unroll
    for (int d = 1; d < 32; d <<= 1) {
        int t = __shfl_up_sync(0xFFFFFFFFu, s, d);
        if (lane >= d) s += t;
    }
    if (lane == 31) wsums[wid] = s;
    __syncthreads();
    if (tid == 0) {
        int run = 0;
#pragma unroll
        for (int w8 = 0; w8 < 8; w8++) { int t = wsums[w8]; wsums[w8] = run; run += t; }
        base_s = atomicAdd(&g_total, run);
    }
    __syncthreads();
    int excl = base_s + wsums[wid] + s - v;
    if (i < n) { g_off[i] = excl; g_cur[i] = excl; }
}

__global__ void fill_kernel(const int* __restrict__ src, const int* __restrict__ tgt, int E) {
    int e = blockIdx.x * blockDim.x + threadIdx.x;
    if (e >= E) return;
    int t = tgt[e];
    int pos = atomicAdd(&g_cur[t], 1);
    g_csr[pos] = src[e];
}

// ---------------- weight prep: transpose + split into interleaved fragment float4 ----------------
__global__ void prep_w_kernel(const float* __restrict__ sWl, const float* __restrict__ sWr,
                              const float* __restrict__ m0, const float* __restrict__ m1,
                              const float* __restrict__ m2) {
    int i = blockIdx.x * blockDim.x + threadIdx.x;
    if (i >= NPAIRS) return;
    int off, K;
    const float* mat;
    if (i < 24576)        { int L = i / 8192;           off = L * 8192;           mat = sWl + L * 16384; K = 128; }
    else if (i < 49152)   { int L = (i - 24576) / 8192; off = 24576 + L * 8192;   mat = sWr + L * 16384; K = 128; }
    else if (i < 53248)   { off = MP0; mat = m0; K = 64; }
    else if (i < 61440)   { off = MP1; mat = m1; K = 128; }
    else                  { off = MP2; mat = m2; K = 128; }
    int li   = i - off;
    int lane = li & 31;
    int nt   = (li >> 5) & 15;
    int kt   = li >> 9;
    int g4 = lane >> 2, t4 = lane & 3;
    int c = nt * 8 + g4;
    int k = kt * 8 + t4;
    float v0 = mat[c * K + k];
    float v1 = mat[c * K + k + 4];
    float h0, l0, h1, l1;
    split_tf32(v0, h0, l0);
    split_tf32(v1, h1, l1);
    *(float4*)&g_wf[(size_t)i * 4] = make_float4(h0, h1, l0, l1);
}

// ---------------- gather aggregation (segment mean), warp per node ----------------
// SLOT >= 0: apply relu(bn) with g_scaleS[SLOT]/g_shiftS[SLOT] to each neighbor row element.
template<int SLOT>
__global__ __launch_bounds__(256) void gather_agg_kernel(const float* __restrict__ h,
                                                         float* __restrict__ agg, int n) {
    int lane = threadIdx.x & 31;
    int v = blockIdx.x * 8 + (threadIdx.x >> 5);
    if (v >= n) return;
    int d0 = g_off[v];
    int c = g_cnt[v];
    int d1 = d0 + c;
    float4 sc, sh;
    if (SLOT >= 0) {
        sc = *(const float4*)&g_scaleS[SLOT][lane * 4];
        sh = *(const float4*)&g_shiftS[SLOT][lane * 4];
    }
    float4 acc = make_float4(0.f, 0.f, 0.f, 0.f);
    for (int j0 = d0; j0 < d1; j0 += 32) {
        int m = d1 - j0; if (m > 32) m = 32;
        int ul = (j0 + lane < d1) ? g_csr[j0 + lane] : 0;
        for (int t = 0; t < m; t++) {
            int u = __shfl_sync(0xFFFFFFFFu, ul, t);
            float4 x = *(const float4*)(h + (size_t)u * HID + lane * 4);
            if (SLOT >= 0) {
                x.x = fmaxf(x.x * sc.x + sh.x, 0.f);
                x.y = fmaxf(x.y * sc.y + sh.y, 0.f);
                x.z = fmaxf(x.z * sc.z + sh.z, 0.f);
                x.w = fmaxf(x.w * sc.w + sh.w, 0.f);
            }
            acc.x += x.x; acc.y += x.y; acc.z += x.z; acc.w += x.w;
        }
    }
    float inv = 1.0f / (float)(c > 0 ? c : 1);
    acc.x *= inv; acc.y *= inv; acc.z *= inv; acc.w *= inv;
    *(float4*)(agg + (size_t)v * HID + lane * 4) = acc;
}

// ---------------- gate branch ----------------
__global__ void normalize_alpha_kernel(const float* __restrict__ alpha, int n) {
    int v = blockIdx.x * blockDim.x + threadIdx.x;
    if (v >= n) return;
    const float4* a = (const float4*)(alpha + (size_t)v * PROTO);
    float4 vals[16];
    float ss = 0.f;
#pragma unroll
    for (int i = 0; i < 16; i++) {
        vals[i] = a[i];
        ss += vals[i].x * vals[i].x + vals[i].y * vals[i].y +
              vals[i].z * vals[i].z + vals[i].w * vals[i].w;
    }
    float inv = 1.0f / fmaxf(sqrtf(ss), 1e-12f);
    float4* o = (float4*)(g_an + (size_t)v * PROTO);
#pragma unroll
    for (int i = 0; i < 16; i++) {
        float4 t = vals[i];
        t.x *= inv; t.y *= inv; t.z *= inv; t.w *= inv;
        o[i] = t;
    }
}

__global__ __launch_bounds__(256) void gate_gather_kernel(const float* __restrict__ temp,
                                                          float* __restrict__ out, int n) {
    int lane = threadIdx.x & 31;
    int v = blockIdx.x * 8 + (threadIdx.x >> 5);
    if (v >= n) return;
    int d0 = g_off[v];
    int c = g_cnt[v];
    int d1 = d0 + c;
    float2 acc = make_float2(0.f, 0.f);
    for (int j0 = d0; j0 < d1; j0 += 32) {
        int m = d1 - j0; if (m > 32) m = 32;
        int ul = (j0 + lane < d1) ? g_csr[j0 + lane] : 0;
        for (int t = 0; t < m; t++) {
            int u = __shfl_sync(0xFFFFFFFFu, ul, t);
            float2 x = *(const float2*)(g_an + (size_t)u * PROTO + lane * 2);
            acc.x += x.x; acc.y += x.y;
        }
    }
    float2 av = *(const float2*)(g_an + (size_t)v * PROTO + lane * 2);
    float d = acc.x * av.x + acc.y * av.y;
#pragma unroll
    for (int s = 16; s > 0; s >>= 1) d += __shfl_down_sync(0xFFFFFFFFu, d, s);
    if (lane == 0) {
        float tv = __ldg(temp);
        float m = (1.0f + d) / (float)(c + 1);
        out[v] = 1.0f / (1.0f + expf(-tv * m));
    }
}

// ---------------- 3xTF32 tensor-core GEMM v4 ----------------
// C[r][c] = bias[c] + sum_k A1'[r][k]*W1[c][k] (+ A2'[r][k]*W2[c][k])
// A': optional fused BN+act on the A input (TRS = slot, TRA: 0 relu, 1 sigmoid).
//   single (DUAL=0): transform applies to A1; DUAL=1: transform applies to A2 (relu).
// A in smem raw->transformed fp32, double buffered; B direct LDG.128 evict_last.
#define ASZ 2304
template<int K, bool DUAL, int STATS, int TRS, int TRA>
__global__ __launch_bounds__(256, 3) void mma_gemm_kernel(
    const float* __restrict__ A1, const float* __restrict__ A2,
    int w1p, int w2p,
    const float* __restrict__ bias, float* __restrict__ C, int n)
{
    __shared__ float As[2 * ASZ];
    __shared__ float ssum[HID], ssq[HID];

    const int tid  = threadIdx.x;
    const int lane = tid & 31;
    const int w    = tid >> 5;
    const int row0 = blockIdx.x * 64;
    const int mtile = w & 3;
    const int nhalf = w >> 2;
    const int nb    = nhalf * 64;
    const int t4 = lane & 3;
    const int g4 = lane >> 2;

    if (STATS >= 0 && tid < HID) { ssum[tid] = 0.f; ssq[tid] = 0.f; }

    float acc[8][4];
#pragma unroll
    for (int j = 0; j < 8; j++) {
        int c0 = nb + j * 8 + 2 * t4;
        float b0 = bias[c0], b1 = bias[c0 + 1];
        acc[j][0] = b0; acc[j][1] = b1; acc[j][2] = b0; acc[j][3] = b1;
    }

    constexpr int NCH = K / KC;
    constexpr int TOT = DUAL ? 2 * NCH : NCH;

    const int ar0 = tid >> 3;            // row 0..31
    const int akq = tid & 7;             // k-quad 0..7
    const int ar1 = ar0 + 32;
    const int gr0 = row0 + ar0, gr1 = row0 + ar1;

    // transform applied to the A stream of chunk `cc`?
    auto xform = [&](float4& v, int k0) {
        if (TRS >= 0) {
            int cb = k0 + akq * 4;
            float4 sc = *(const float4*)&g_scaleS[TRS][cb];
            float4 sh = *(const float4*)&g_shiftS[TRS][cb];
            v.x = v.x * sc.x + sh.x; v.y = v.y * sc.y + sh.y;
            v.z = v.z * sc.z + sh.z; v.w = v.w * sc.w + sh.w;
            if (TRA == 0) {
                v.x = fmaxf(v.x, 0.f); v.y = fmaxf(v.y, 0.f);
                v.z = fmaxf(v.z, 0.f); v.w = fmaxf(v.w, 0.f);
            } else {
                v.x = 1.f / (1.f + expf(-v.x)); v.y = 1.f / (1.f + expf(-v.y));
                v.z = 1.f / (1.f + expf(-v.z)); v.w = 1.f / (1.f + expf(-v.w));
            }
        }
    };

    // ---- prologue: chunk 0 (always A1) ----
    {
        float4 a0 = (gr0 < n) ? ldg_ef4(A1 + (size_t)gr0 * K + akq * 4) : make_float4(0, 0, 0, 0);
        float4 a1 = (gr1 < n) ? ldg_ef4(A1 + (size_t)gr1 * K + akq * 4) : make_float4(0, 0, 0, 0);
        if (!DUAL) { if (gr0 < n) xform(a0, 0); if (gr1 < n) xform(a1, 0); }
        *(float4*)&As[ar0 * 36 + akq * 4] = a0;
        *(float4*)&As[ar1 * 36 + akq * 4] = a1;
    }
    __syncthreads();

#pragma unroll 1
    for (int ch = 0; ch < TOT; ch++) {
        const int cur = ch & 1, nxt = cur ^ 1;
        const bool more = (ch + 1 < TOT);
        float4 p0, p1;
        bool tr_nxt = false;
        int k0n = 0;
        if (more) {
            int cn = ch + 1;
            bool isA2 = (DUAL && cn >= NCH);
            const float* Ap = isA2 ? A2 : A1;
            k0n = (cn % NCH) * KC;
            p0 = (gr0 < n) ? ldg_ef4(Ap + (size_t)gr0 * K + k0n + akq * 4) : make_float4(0, 0, 0, 0);
            p1 = (gr1 < n) ? ldg_ef4(Ap + (size_t)gr1 * K + k0n + akq * 4) : make_float4(0, 0, 0, 0);
            tr_nxt = DUAL ? isA2 : true;
        }
        // ---- math on cur ----
        {
            const float* Ac = As + cur * ASZ;
            const int wbase = ((DUAL && ch >= NCH) ? w2p : w1p) + (ch % NCH) * 2048;
#pragma unroll
            for (int kt = 0; kt < 4; kt++) {
                int base = (mtile * 16 + g4) * 36 + kt * 8 + t4;
                float ra0 = Ac[base], ra1 = Ac[base + 8 * 36];
                float ra2 = Ac[base + 4], ra3 = Ac[base + 8 * 36 + 4];
                float h0, l0, h1, l1, h2, l2, h3, l3;
                split_tf32(ra0, h0, l0); split_tf32(ra1, h1, l1);
                split_tf32(ra2, h2, l2); split_tf32(ra3, h3, l3);
                uint32 ah0 = __float_as_uint(h0), ah1 = __float_as_uint(h1);
                uint32 ah2 = __float_as_uint(h2), ah3 = __float_as_uint(h3);
                uint32 al0 = __float_as_uint(l0), al1 = __float_as_uint(l1);
                uint32 al2 = __float_as_uint(l2), al3 = __float_as_uint(l3);
#pragma unroll
                for (int j = 0; j < 8; j++) {
                    int jg = nhalf * 8 + j;
                    int pidx = wbase + (kt * 16 + jg) * 32 + lane;
                    float4 bf = ldg_el4(g_wf + (size_t)pidx * 4);
                    uint32 bh0 = __float_as_uint(bf.x), bh1 = __float_as_uint(bf.y);
                    uint32 bl0 = __float_as_uint(bf.z), bl1 = __float_as_uint(bf.w);
                    mma_tf32(acc[j], ah0, ah1, ah2, ah3, bh0, bh1);
                    mma_tf32(acc[j], ah0, ah1, ah2, ah3, bl0, bl1);
                    mma_tf32(acc[j], al0, al1, al2, al3, bh0, bh1);
                }
            }
        }
        if (more) {
            if (tr_nxt) { if (gr0 < n) xform(p0, k0n); if (gr1 < n) xform(p1, k0n); }
            *(float4*)&As[nxt * ASZ + ar0 * 36 + akq * 4] = p0;
            *(float4*)&As[nxt * ASZ + ar1 * 36 + akq * 4] = p1;
        }
        __syncthreads();
    }

    // ---- epilogue: store + fused stats ----
    int r0 = row0 + mtile * 16 + g4;
    int r1 = r0 + 8;
#pragma unroll
    for (int j = 0; j < 8; j++) {
        int c0 = nb + j * 8 + 2 * t4;
        float s0 = 0.f, s1 = 0.f, q0 = 0.f, q1 = 0.f;
        if (r0 < n) {
            *(float2*)(C + (size_t)r0 * HID + c0) = make_float2(acc[j][0], acc[j][1]);
            s0 += acc[j][0]; s1 += acc[j][1];
            q0 += acc[j][0] * acc[j][0]; q1 += acc[j][1] * acc[j][1];
        }
        if (r1 < n) {
            *(float2*)(C + (size_t)r1 * HID + c0) = make_float2(acc[j][2], acc[j][3]);
            s0 += acc[j][2]; s1 += acc[j][3];
            q0 += acc[j][2] * acc[j][2]; q1 += acc[j][3] * acc[j][3];
        }
        if (STATS >= 0) {
            atomicAdd(&ssum[c0], s0); atomicAdd(&ssum[c0 + 1], s1);
            atomicAdd(&ssq[c0], q0);  atomicAdd(&ssq[c0 + 1], q1);
        }
    }
    if (STATS >= 0) {
        __syncthreads();
        if (tid < HID) {
            atomicAdd(&g_sum[STATS * HID + tid], ssum[tid]);
            atomicAdd(&g_sumsq[STATS * HID + tid], ssq[tid]);
        }
    }
}

// ---------------- BN finalize ----------------
__global__ void stats_final_kernel(const float* __restrict__ gamma, const float* __restrict__ beta,
                                   float inv_n, int slot) {
    int c = threadIdx.x;
    float mu = g_sum[slot * HID + c] * inv_n;
    float var = g_sumsq[slot * HID + c] * inv_n - mu * mu;
    float sc = gamma[c] * rsqrtf(var + BN_EPS);
    g_scaleS[slot][c] = sc;
    g_shiftS[slot][c] = beta[c] - mu * sc;
}

// ---------------- classifier + log_softmax ----------------
__global__ __launch_bounds__(256) void classifier_kernel(
    const float* __restrict__ hg, const float* __restrict__ hp,
    const float* __restrict__ Wc, const float* __restrict__ bc,
    float* __restrict__ out, int n)
{
    __shared__ float wcs[40 * 256];
    __shared__ float bcs[40];
    int tid = threadIdx.x;
    for (int i = tid; i < 40 * 256; i += 256) wcs[i] = Wc[i];
    if (tid < 40) bcs[tid] = bc[tid];
    __syncthreads();
    int r = blockIdx.x * 256 + tid;
    if (r >= n) return;

    float acc[40];
#pragma unroll
    for (int o = 0; o < 40; o++) acc[o] = bcs[o];

    for (int half = 0; half < 2; half++) {
        const float* src = half ? hp : hg;
        for (int k4 = 0; k4 < 32; k4++) {
            float4 z = *(const float4*)(src + (size_t)r * HID + k4 * 4);
            z.x = fmaxf(z.x, 0.f); z.y = fmaxf(z.y, 0.f);
            z.z = fmaxf(z.z, 0.f); z.w = fmaxf(z.w, 0.f);
            int kb = half * 128 + k4 * 4;
#pragma unroll
            for (int o = 0; o < 40; o++) {
                float4 wv = *(float4*)&wcs[o * 256 + kb];
                acc[o] += z.x * wv.x + z.y * wv.y + z.z * wv.z + z.w * wv.w;
            }
        }
    }
    float m = acc[0];
#pragma unroll
    for (int o = 1; o < 40; o++) m = fmaxf(m, acc[o]);
    float s = 0.f;
#pragma unroll
    for (int o = 0; o < 40; o++) s += expf(acc[o] - m);
    float lse = m + logf(s);
    float* op = out + (size_t)r * 40;
#pragma unroll
    for (int o = 0; o < 40; o++) op[o] = acc[o] - lse;
}

// ---------------- launcher ----------------
extern "C" void kernel_launch(void* const* d_in, const int* in_sizes, int n_in,
                              void* d_out, int out_size) {
    const float* x           = (const float*)d_in[0];
    const float* alpha       = (const float*)d_in[1];
    const int*   ei          = (const int*)d_in[2];
    const float* sage_Wl     = (const float*)d_in[3];
    const float* sage_bl     = (const float*)d_in[4];
    const float* sage_Wr     = (const float*)d_in[5];
    const float* sage_bng    = (const float*)d_in[6];
    const float* sage_bnb    = (const float*)d_in[7];
    const float* mlp_W0      = (const float*)d_in[8];
    const float* mlp_b0      = (const float*)d_in[9];
    const float* mlp_W1      = (const float*)d_in[10];
    const float* mlp_b1      = (const float*)d_in[11];
    const float* mlp_W2      = (const float*)d_in[12];
    const float* mlp_b2      = (const float*)d_in[13];
    const float* mlp_bng     = (const float*)d_in[14];
    const float* mlp_bnb     = (const float*)d_in[15];
    const float* W_cls       = (const float*)d_in[16];
    const float* b_cls       = (const float*)d_in[17];
    const float* temperature = (const float*)d_in[18];

    int n = in_sizes[0] / HID;
    int E = in_sizes[2] / 2;
    const int* src = ei;
    const int* tgt = ei + E;
    float* out = (float*)d_out;

    float *h1, *h2, *agg, *p, *p2;
    cudaGetSymbolAddress((void**)&h1,  g_h1);
    cudaGetSymbolAddress((void**)&h2,  g_h2);
    cudaGetSymbolAddress((void**)&agg, g_agg);
    cudaGetSymbolAddress((void**)&p,   g_p);
    cudaGetSymbolAddress((void**)&p2,  g_p2);

    const int TB = 256;
    int nodeBlocks = (n + TB - 1) / TB;
    int warpNodeBlocks = (n + 7) / 8;
    int gemmBlocks = (n + 63) / 64;
    float inv_n = 1.0f / (float)n;
    int eBlocks = (E + TB - 1) / TB;

    // ---- proto branch FIRST (gemm at launch index 3 -> ncu capture window) ----
    init_kernel<<<2, TB>>>();                                                              // 0
    prep_w_kernel<<<(NPAIRS + TB - 1) / TB, TB>>>(sage_Wl, sage_Wr, mlp_W0, mlp_W1, mlp_W2); // 1
    normalize_alpha_kernel<<<nodeBlocks, TB>>>(alpha, n);                                  // 2
    mma_gemm_kernel<64, false, 2, -1, 0><<<gemmBlocks, TB>>>(alpha, nullptr, MP0, 0, mlp_b0, p, n); // 3
    stats_final_kernel<<<1, HID>>>(mlp_bng, mlp_bnb, inv_n, 2);
    mma_gemm_kernel<128, false, 3, 2, 1><<<gemmBlocks, TB>>>(p, nullptr, MP1, 0, mlp_b1, p2, n);
    stats_final_kernel<<<1, HID>>>(mlp_bng + HID, mlp_bnb + HID, inv_n, 3);
    mma_gemm_kernel<128, false, -1, 3, 1><<<gemmBlocks, TB>>>(p2, nullptr, MP2, 0, mlp_b2, p, n);

    // ---- CSR build ----
    zero_cnt_kernel<<<nodeBlocks, TB>>>(n);
    count_kernel<<<eBlocks, TB>>>(tgt, E);
    alloc_kernel<<<nodeBlocks, TB>>>(n);
    fill_kernel<<<eBlocks, TB>>>(src, tgt, E);

    // ---- SAGE layer 0 (inputs raw x) ----
    gather_agg_kernel<-1><<<warpNodeBlocks, TB>>>(x, agg, n);
    mma_gemm_kernel<128, true, 0, -1, 0><<<gemmBlocks, TB>>>(agg, x, WPL(0), WPR(0), sage_bl, h1, n);
    stats_final_kernel<<<1, HID>>>(sage_bng, sage_bnb, inv_n, 0);

    // ---- SAGE layer 1 (h1 raw, bn slot0 + relu fused into consumers) ----
    gather_agg_kernel<0><<<warpNodeBlocks, TB>>>(h1, agg, n);
    mma_gemm_kernel<128, true, 1, 0, 0><<<gemmBlocks, TB>>>(agg, h1, WPL(1), WPR(1), sage_bl + HID, h2, n);
    stats_final_kernel<<<1, HID>>>(sage_bng + HID, sage_bnb + HID, inv_n, 1);

    // ---- SAGE layer 2 (h2 raw, bn slot1 + relu fused; output raw) ----
    gather_agg_kernel<1><<<warpNodeBlocks, TB>>>(h2, agg, n);
    mma_gemm_kernel<128, true, -1, 1, 0><<<gemmBlocks, TB>>>(agg, h2, WPL(2), WPR(2), sage_bl + 2 * HID, h1, n);

    // ---- fusion + classifier + log_softmax ----
    classifier_kernel<<<nodeBlocks, TB>>>(h1, p, W_cls, b_cls, out, n);

    // ---- gate (gather form) ----
    gate_gather_kernel<<<warpNodeBlocks, TB>>>(temperature, out + (size_t)n * 40, n);
}

// round 11
// speedup vs baseline: 1.0389x; 1.0389x over previous
#include <cuda_runtime.h>
#include <cuda_bf16.h>
#include <math.h>

#define NMAX 100000
#define EMAX 1700000
#define HID 128
#define PROTO 64
#define BN_EPS 1e-5f
#define KC 32

typedef unsigned int uint32;

// ---------------- scratch (device globals: no allocation allowed) ----------------
__device__ float g_h1[NMAX * HID];
__device__ float g_h2[NMAX * HID];
__device__ float g_agg[NMAX * HID];
__device__ float g_p[NMAX * HID];
__device__ float g_p2[NMAX * HID];
__device__ float g_an[NMAX * PROTO];
__device__ int   g_cnt[NMAX];
__device__ int   g_off[NMAX + 1];
__device__ int   g_cur[NMAX];
__device__ int   g_csr[EMAX];
__device__ int   g_total;
__device__ float g_sum[4 * HID];
__device__ float g_sumsq[4 * HID];
__device__ float g_scaleS[4][HID];
__device__ float g_shiftS[4][HID];

// Weights in INTERLEAVED tf32 fragment layout: one float4 per "pair"
//   pair index: ((ktile*16 + ntile)*32 + lane)
//   float4 = { hi(reg0), hi(reg1), lo(reg0), lo(reg1) }
#define WPL(L) ((L) * 8192)
#define WPR(L) (24576 + (L) * 8192)
#define MP0 49152
#define MP1 53248
#define MP2 61440
#define NPAIRS 69632
__device__ float g_wf[NPAIRS * 4];

// ---------------- tf32 + cache-hint helpers ----------------
__device__ __forceinline__ uint32 cvt_tf32(float x) {
    uint32 r;
    asm("cvt.rna.tf32.f32 %0, %1;" : "=r"(r) : "f"(x));
    return r;
}
__device__ __forceinline__ void split_tf32(float x, float& hi, float& lo) {
    uint32 h = cvt_tf32(x);
    hi = __uint_as_float(h);
    lo = __uint_as_float(cvt_tf32(x - hi));
}
__device__ __forceinline__ void mma_tf32(float* c,
                                         uint32 a0, uint32 a1, uint32 a2, uint32 a3,
                                         uint32 b0, uint32 b1) {
    asm volatile("mma.sync.aligned.m16n8k8.row.col.f32.tf32.tf32.f32 "
                 "{%0,%1,%2,%3}, {%4,%5,%6,%7}, {%8,%9}, {%0,%1,%2,%3};"
                 : "+f"(c[0]), "+f"(c[1]), "+f"(c[2]), "+f"(c[3])
                 : "r"(a0), "r"(a1), "r"(a2), "r"(a3), "r"(b0), "r"(b1));
}
__device__ __forceinline__ float4 ldg_ef4(const float* p) {
    float4 v;
    asm("ld.global.nc.L1::evict_first.v4.f32 {%0,%1,%2,%3}, [%4];"
        : "=f"(v.x), "=f"(v.y), "=f"(v.z), "=f"(v.w) : "l"(p));
    return v;
}
__device__ __forceinline__ float4 ldg_el4(const float* p) {
    float4 v;
    asm("ld.global.nc.L1::evict_last.v4.f32 {%0,%1,%2,%3}, [%4];"
        : "=f"(v.x), "=f"(v.y), "=f"(v.z), "=f"(v.w) : "l"(p));
    return v;
}

// ---------------- init ----------------
__global__ void init_kernel() {
    int v = blockIdx.x * blockDim.x + threadIdx.x;
    if (v < 4 * HID) { g_sum[v] = 0.f; g_sumsq[v] = 0.f; }
    if (v == 0) g_total = 0;
}

__global__ void zero_cnt_kernel(int n) {
    int v = blockIdx.x * blockDim.x + threadIdx.x;
    if (v < n) g_cnt[v] = 0;
}
__global__ void count_kernel(const int* __restrict__ tgt, int E) {
    int e = blockIdx.x * blockDim.x + threadIdx.x;
    if (e < E) atomicAdd(&g_cnt[tgt[e]], 1);
}

// ---------------- CSR offset allocation (unordered block bases) ----------------
__global__ void alloc_kernel(int n) {
    __shared__ int wsums[8];
    __shared__ int base_s;
    int tid = threadIdx.x, lane = tid & 31, wid = tid >> 5;
    int i = blockIdx.x * 256 + tid;
    int v = (i < n) ? g_cnt[i] : 0;
    int s = v;
#pragma unroll
    for (int d = 1; d < 32; d <<= 1) {
        int t = __shfl_up_sync(0xFFFFFFFFu, s, d);
        if (lane >= d) s += t;
    }
    if (lane == 31) wsums[wid] = s;
    __syncthreads();
    if (tid == 0) {
        int run = 0;
#pragma unroll
        for (int w8 = 0; w8 < 8; w8++) { int t = wsums[w8]; wsums[w8] = run; run += t; }
        base_s = atomicAdd(&g_total, run);
    }
    __syncthreads();
    int excl = base_s + wsums[wid] + s - v;
    if (i < n) { g_off[i] = excl; g_cur[i] = excl; }
}

__global__ void fill_kernel(const int* __restrict__ src, const int* __restrict__ tgt, int E) {
    int e = blockIdx.x * blockDim.x + threadIdx.x;
    if (e >= E) return;
    int t = tgt[e];
    int pos = atomicAdd(&g_cur[t], 1);
    g_csr[pos] = src[e];
}

// ---------------- weight prep: transpose + split into interleaved fragment float4 ----------------
__global__ void prep_w_kernel(const float* __restrict__ sWl, const float* __restrict__ sWr,
                              const float* __restrict__ m0, const float* __restrict__ m1,
                              const float* __restrict__ m2) {
    int i = blockIdx.x * blockDim.x + threadIdx.x;
    if (i >= NPAIRS) return;
    int off, K;
    const float* mat;
    if (i < 24576)        { int L = i / 8192;           off = L * 8192;           mat = sWl + L * 16384; K = 128; }
    else if (i < 49152)   { int L = (i - 24576) / 8192; off = 24576 + L * 8192;   mat = sWr + L * 16384; K = 128; }
    else if (i < 53248)   { off = MP0; mat = m0; K = 64; }
    else if (i < 61440)   { off = MP1; mat = m1; K = 128; }
    else                  { off = MP2; mat = m2; K = 128; }
    int li   = i - off;
    int lane = li & 31;
    int nt   = (li >> 5) & 15;
    int kt   = li >> 9;
    int g4 = lane >> 2, t4 = lane & 3;
    int c = nt * 8 + g4;
    int k = kt * 8 + t4;
    float v0 = mat[c * K + k];
    float v1 = mat[c * K + k + 4];
    float h0, l0, h1, l1;
    split_tf32(v0, h0, l0);
    split_tf32(v1, h1, l1);
    *(float4*)&g_wf[(size_t)i * 4] = make_float4(h0, h1, l0, l1);
}

// ---------------- gather aggregation (segment mean), warp per node ----------------
template<int SLOT>
__global__ __launch_bounds__(256) void gather_agg_kernel(const float* __restrict__ h,
                                                         float* __restrict__ agg, int n) {
    int lane = threadIdx.x & 31;
    int v = blockIdx.x * 8 + (threadIdx.x >> 5);
    if (v >= n) return;
    int d0 = g_off[v];
    int c = g_cnt[v];
    int d1 = d0 + c;
    float4 sc, sh;
    if (SLOT >= 0) {
        sc = *(const float4*)&g_scaleS[SLOT][lane * 4];
        sh = *(const float4*)&g_shiftS[SLOT][lane * 4];
    }
    float4 acc = make_float4(0.f, 0.f, 0.f, 0.f);
    for (int j0 = d0; j0 < d1; j0 += 32) {
        int m = d1 - j0; if (m > 32) m = 32;
        int ul = (j0 + lane < d1) ? g_csr[j0 + lane] : 0;
        for (int t = 0; t < m; t++) {
            int u = __shfl_sync(0xFFFFFFFFu, ul, t);
            float4 x = *(const float4*)(h + (size_t)u * HID + lane * 4);
            if (SLOT >= 0) {
                x.x = fmaxf(x.x * sc.x + sh.x, 0.f);
                x.y = fmaxf(x.y * sc.y + sh.y, 0.f);
                x.z = fmaxf(x.z * sc.z + sh.z, 0.f);
                x.w = fmaxf(x.w * sc.w + sh.w, 0.f);
            }
            acc.x += x.x; acc.y += x.y; acc.z += x.z; acc.w += x.w;
        }
    }
    float inv = 1.0f / (float)(c > 0 ? c : 1);
    acc.x *= inv; acc.y *= inv; acc.z *= inv; acc.w *= inv;
    *(float4*)(agg + (size_t)v * HID + lane * 4) = acc;
}

// ---------------- gate branch ----------------
__global__ void normalize_alpha_kernel(const float* __restrict__ alpha, int n) {
    int v = blockIdx.x * blockDim.x + threadIdx.x;
    if (v >= n) return;
    const float4* a = (const float4*)(alpha + (size_t)v * PROTO);
    float4 vals[16];
    float ss = 0.f;
#pragma unroll
    for (int i = 0; i < 16; i++) {
        vals[i] = a[i];
        ss += vals[i].x * vals[i].x + vals[i].y * vals[i].y +
              vals[i].z * vals[i].z + vals[i].w * vals[i].w;
    }
    float inv = 1.0f / fmaxf(sqrtf(ss), 1e-12f);
    float4* o = (float4*)(g_an + (size_t)v * PROTO);
#pragma unroll
    for (int i = 0; i < 16; i++) {
        float4 t = vals[i];
        t.x *= inv; t.y *= inv; t.z *= inv; t.w *= inv;
        o[i] = t;
    }
}

__global__ __launch_bounds__(256) void gate_gather_kernel(const float* __restrict__ temp,
                                                          float* __restrict__ out, int n) {
    int lane = threadIdx.x & 31;
    int v = blockIdx.x * 8 + (threadIdx.x >> 5);
    if (v >= n) return;
    int d0 = g_off[v];
    int c = g_cnt[v];
    int d1 = d0 + c;
    float2 acc = make_float2(0.f, 0.f);
    for (int j0 = d0; j0 < d1; j0 += 32) {
        int m = d1 - j0; if (m > 32) m = 32;
        int ul = (j0 + lane < d1) ? g_csr[j0 + lane] : 0;
        for (int t = 0; t < m; t++) {
            int u = __shfl_sync(0xFFFFFFFFu, ul, t);
            float2 x = *(const float2*)(g_an + (size_t)u * PROTO + lane * 2);
            acc.x += x.x; acc.y += x.y;
        }
    }
    float2 av = *(const float2*)(g_an + (size_t)v * PROTO + lane * 2);
    float d = acc.x * av.x + acc.y * av.y;
#pragma unroll
    for (int s = 16; s > 0; s >>= 1) d += __shfl_down_sync(0xFFFFFFFFu, d, s);
    if (lane == 0) {
        float tv = __ldg(temp);
        float m = (1.0f + d) / (float)(c + 1);
        out[v] = 1.0f / (1.0f + expf(-tv * m));
    }
}

// ---------------- 3xTF32 tensor-core GEMM v5: 128-row tile, warp m32n64, B reuse x2 ----------------
// C[r][c] = bias[c] + sum_k A1'[r][k]*W1[c][k] (+ A2'[r][k]*W2[c][k])
// block 256 thr = 8 warps; 128 rows x 128 cols; warp = m32 x n64 (two m16 tiles).
// Each B fragment (one LDG.128) feeds 6 mmas.
#define ASZ5 4608
template<int K, bool DUAL, int STATS, int TRS, int TRA>
__global__ __launch_bounds__(256, 2) void mma_gemm_kernel(
    const float* __restrict__ A1, const float* __restrict__ A2,
    int w1p, int w2p,
    const float* __restrict__ bias, float* __restrict__ C, int n)
{
    __shared__ float As[2 * ASZ5];
    __shared__ float ssum[HID], ssq[HID];

    const int tid  = threadIdx.x;
    const int lane = tid & 31;
    const int w    = tid >> 5;
    const int row0 = blockIdx.x * 128;
    const int mt    = (w & 3) * 32;      // rows mt..mt+31 (m16 tiles at mt, mt+16)
    const int nhalf = w >> 2;
    const int nb    = nhalf * 64;
    const int t4 = lane & 3;
    const int g4 = lane >> 2;

    if (STATS >= 0 && tid < HID) { ssum[tid] = 0.f; ssq[tid] = 0.f; }

    float acc[2][8][4];
#pragma unroll
    for (int j = 0; j < 8; j++) {
        int c0 = nb + j * 8 + 2 * t4;
        float b0 = bias[c0], b1 = bias[c0 + 1];
#pragma unroll
        for (int m2 = 0; m2 < 2; m2++) {
            acc[m2][j][0] = b0; acc[m2][j][1] = b1; acc[m2][j][2] = b0; acc[m2][j][3] = b1;
        }
    }

    constexpr int NCH = K / KC;
    constexpr int TOT = DUAL ? 2 * NCH : NCH;

    // A loader: 4 float4 per thread per chunk: idx = tid + i*256, row = idx>>3, quad = idx&7
    auto xform = [&](float4& v, int cb) {
        if (TRS >= 0) {
            float4 sc = *(const float4*)&g_scaleS[TRS][cb];
            float4 sh = *(const float4*)&g_shiftS[TRS][cb];
            v.x = v.x * sc.x + sh.x; v.y = v.y * sc.y + sh.y;
            v.z = v.z * sc.z + sh.z; v.w = v.w * sc.w + sh.w;
            if (TRA == 0) {
                v.x = fmaxf(v.x, 0.f); v.y = fmaxf(v.y, 0.f);
                v.z = fmaxf(v.z, 0.f); v.w = fmaxf(v.w, 0.f);
            } else {
                v.x = 1.f / (1.f + expf(-v.x)); v.y = 1.f / (1.f + expf(-v.y));
                v.z = 1.f / (1.f + expf(-v.z)); v.w = 1.f / (1.f + expf(-v.w));
            }
        }
    };

    auto loadA = [&](int ch, float4* pv) {
        bool isA2 = (DUAL && ch >= NCH);
        const float* Ap = isA2 ? A2 : A1;
        int k0 = (ch % NCH) * KC;
        bool tr = DUAL ? isA2 : true;
#pragma unroll
        for (int i = 0; i < 4; i++) {
            int idx = tid + i * 256;
            int arow = idx >> 3, aq = idx & 7;
            int gr = row0 + arow;
            float4 v = (gr < n) ? ldg_ef4(Ap + (size_t)gr * K + k0 + aq * 4) : make_float4(0, 0, 0, 0);
            if (tr && gr < n) xform(v, k0 + aq * 4);
            pv[i] = v;
        }
    };
    auto storeA = [&](int buf, const float4* pv) {
#pragma unroll
        for (int i = 0; i < 4; i++) {
            int idx = tid + i * 256;
            int arow = idx >> 3, aq = idx & 7;
            *(float4*)&As[buf * ASZ5 + arow * 36 + aq * 4] = pv[i];
        }
    };

    // ---- prologue: chunk 0 ----
    {
        float4 pv[4];
        loadA(0, pv);
        storeA(0, pv);
    }
    __syncthreads();

#pragma unroll 1
    for (int ch = 0; ch < TOT; ch++) {
        const int cur = ch & 1, nxt = cur ^ 1;
        const bool more = (ch + 1 < TOT);
        float4 pv[4];
        if (more) loadA(ch + 1, pv);
        // ---- math on cur ----
        {
            const float* Ac = As + cur * ASZ5;
            const int wbase = ((DUAL && ch >= NCH) ? w2p : w1p) + (ch % NCH) * 2048;
#pragma unroll
            for (int kt = 0; kt < 4; kt++) {
                uint32 ah[2][4], al[2][4];
#pragma unroll
                for (int m2 = 0; m2 < 2; m2++) {
                    int base = (mt + m2 * 16 + g4) * 36 + kt * 8 + t4;
                    float ra0 = Ac[base], ra1 = Ac[base + 8 * 36];
                    float ra2 = Ac[base + 4], ra3 = Ac[base + 8 * 36 + 4];
                    float h0, l0, h1, l1, h2, l2, h3, l3;
                    split_tf32(ra0, h0, l0); split_tf32(ra1, h1, l1);
                    split_tf32(ra2, h2, l2); split_tf32(ra3, h3, l3);
                    ah[m2][0] = __float_as_uint(h0); ah[m2][1] = __float_as_uint(h1);
                    ah[m2][2] = __float_as_uint(h2); ah[m2][3] = __float_as_uint(h3);
                    al[m2][0] = __float_as_uint(l0); al[m2][1] = __float_as_uint(l1);
                    al[m2][2] = __float_as_uint(l2); al[m2][3] = __float_as_uint(l3);
                }
#pragma unroll
                for (int j = 0; j < 8; j++) {
                    int jg = nhalf * 8 + j;
                    int pidx = wbase + (kt * 16 + jg) * 32 + lane;
                    float4 bf = ldg_el4(g_wf + (size_t)pidx * 4);
                    uint32 bh0 = __float_as_uint(bf.x), bh1 = __float_as_uint(bf.y);
                    uint32 bl0 = __float_as_uint(bf.z), bl1 = __float_as_uint(bf.w);
#pragma unroll
                    for (int m2 = 0; m2 < 2; m2++) {
                        mma_tf32(acc[m2][j], ah[m2][0], ah[m2][1], ah[m2][2], ah[m2][3], bh0, bh1);
                        mma_tf32(acc[m2][j], ah[m2][0], ah[m2][1], ah[m2][2], ah[m2][3], bl0, bl1);
                        mma_tf32(acc[m2][j], al[m2][0], al[m2][1], al[m2][2], al[m2][3], bh0, bh1);
                    }
                }
            }
        }
        if (more) storeA(nxt, pv);
        __syncthreads();
    }

    // ---- epilogue: store + fused stats ----
#pragma unroll
    for (int j = 0; j < 8; j++) {
        int c0 = nb + j * 8 + 2 * t4;
        float s0 = 0.f, s1 = 0.f, q0 = 0.f, q1 = 0.f;
#pragma unroll
        for (int m2 = 0; m2 < 2; m2++) {
            int r0 = row0 + mt + m2 * 16 + g4;
            int r1 = r0 + 8;
            if (r0 < n) {
                *(float2*)(C + (size_t)r0 * HID + c0) = make_float2(acc[m2][j][0], acc[m2][j][1]);
                s0 += acc[m2][j][0]; s1 += acc[m2][j][1];
                q0 += acc[m2][j][0] * acc[m2][j][0]; q1 += acc[m2][j][1] * acc[m2][j][1];
            }
            if (r1 < n) {
                *(float2*)(C + (size_t)r1 * HID + c0) = make_float2(acc[m2][j][2], acc[m2][j][3]);
                s0 += acc[m2][j][2]; s1 += acc[m2][j][3];
                q0 += acc[m2][j][2] * acc[m2][j][2]; q1 += acc[m2][j][3] * acc[m2][j][3];
            }
        }
        if (STATS >= 0) {
            atomicAdd(&ssum[c0], s0); atomicAdd(&ssum[c0 + 1], s1);
            atomicAdd(&ssq[c0], q0);  atomicAdd(&ssq[c0 + 1], q1);
        }
    }
    if (STATS >= 0) {
        __syncthreads();
        if (tid < HID) {
            atomicAdd(&g_sum[STATS * HID + tid], ssum[tid]);
            atomicAdd(&g_sumsq[STATS * HID + tid], ssq[tid]);
        }
    }
}

// ---------------- BN finalize ----------------
__global__ void stats_final_kernel(const float* __restrict__ gamma, const float* __restrict__ beta,
                                   float inv_n, int slot) {
    int c = threadIdx.x;
    float mu = g_sum[slot * HID + c] * inv_n;
    float var = g_sumsq[slot * HID + c] * inv_n - mu * mu;
    float sc = gamma[c] * rsqrtf(var + BN_EPS);
    g_scaleS[slot][c] = sc;
    g_shiftS[slot][c] = beta[c] - mu * sc;
}

// ---------------- classifier + log_softmax ----------------
__global__ __launch_bounds__(256) void classifier_kernel(
    const float* __restrict__ hg, const float* __restrict__ hp,
    const float* __restrict__ Wc, const float* __restrict__ bc,
    float* __restrict__ out, int n)
{
    __shared__ float wcs[40 * 256];
    __shared__ float bcs[40];
    int tid = threadIdx.x;
    for (int i = tid; i < 40 * 256; i += 256) wcs[i] = Wc[i];
    if (tid < 40) bcs[tid] = bc[tid];
    __syncthreads();
    int r = blockIdx.x * 256 + tid;
    if (r >= n) return;

    float acc[40];
#pragma unroll
    for (int o = 0; o < 40; o++) acc[o] = bcs[o];

    for (int half = 0; half < 2; half++) {
        const float* src = half ? hp : hg;
        for (int k4 = 0; k4 < 32; k4++) {
            float4 z = *(const float4*)(src + (size_t)r * HID + k4 * 4);
            z.x = fmaxf(z.x, 0.f); z.y = fmaxf(z.y, 0.f);
            z.z = fmaxf(z.z, 0.f); z.w = fmaxf(z.w, 0.f);
            int kb = half * 128 + k4 * 4;
#pragma unroll
            for (int o = 0; o < 40; o++) {
                float4 wv = *(float4*)&wcs[o * 256 + kb];
                acc[o] += z.x * wv.x + z.y * wv.y + z.z * wv.z + z.w * wv.w;
            }
        }
    }
    float m = acc[0];
#pragma unroll
    for (int o = 1; o < 40; o++) m = fmaxf(m, acc[o]);
    float s = 0.f;
#pragma unroll
    for (int o = 0; o < 40; o++) s += expf(acc[o] - m);
    float lse = m + logf(s);
    float* op = out + (size_t)r * 40;
#pragma unroll
    for (int o = 0; o < 40; o++) op[o] = acc[o] - lse;
}

// ---------------- launcher ----------------
extern "C" void kernel_launch(void* const* d_in, const int* in_sizes, int n_in,
                              void* d_out, int out_size) {
    const float* x           = (const float*)d_in[0];
    const float* alpha       = (const float*)d_in[1];
    const int*   ei          = (const int*)d_in[2];
    const float* sage_Wl     = (const float*)d_in[3];
    const float* sage_bl     = (const float*)d_in[4];
    const float* sage_Wr     = (const float*)d_in[5];
    const float* sage_bng    = (const float*)d_in[6];
    const float* sage_bnb    = (const float*)d_in[7];
    const float* mlp_W0      = (const float*)d_in[8];
    const float* mlp_b0      = (const float*)d_in[9];
    const float* mlp_W1      = (const float*)d_in[10];
    const float* mlp_b1      = (const float*)d_in[11];
    const float* mlp_W2      = (const float*)d_in[12];
    const float* mlp_b2      = (const float*)d_in[13];
    const float* mlp_bng     = (const float*)d_in[14];
    const float* mlp_bnb     = (const float*)d_in[15];
    const float* W_cls       = (const float*)d_in[16];
    const float* b_cls       = (const float*)d_in[17];
    const float* temperature = (const float*)d_in[18];

    int n = in_sizes[0] / HID;
    int E = in_sizes[2] / 2;
    const int* src = ei;
    const int* tgt = ei + E;
    float* out = (float*)d_out;

    float *h1, *h2, *agg, *p, *p2;
    cudaGetSymbolAddress((void**)&h1,  g_h1);
    cudaGetSymbolAddress((void**)&h2,  g_h2);
    cudaGetSymbolAddress((void**)&agg, g_agg);
    cudaGetSymbolAddress((void**)&p,   g_p);
    cudaGetSymbolAddress((void**)&p2,  g_p2);

    const int TB = 256;
    int nodeBlocks = (n + TB - 1) / TB;
    int warpNodeBlocks = (n + 7) / 8;
    int gemmBlocks = (n + 127) / 128;
    float inv_n = 1.0f / (float)n;
    int eBlocks = (E + TB - 1) / TB;

    // ---- proto branch FIRST (gemm at launch index 3 -> ncu capture window) ----
    init_kernel<<<2, TB>>>();                                                              // 0
    prep_w_kernel<<<(NPAIRS + TB - 1) / TB, TB>>>(sage_Wl, sage_Wr, mlp_W0, mlp_W1, mlp_W2); // 1
    normalize_alpha_kernel<<<nodeBlocks, TB>>>(alpha, n);                                  // 2
    mma_gemm_kernel<64, false, 2, -1, 0><<<gemmBlocks, TB>>>(alpha, nullptr, MP0, 0, mlp_b0, p, n); // 3
    stats_final_kernel<<<1, HID>>>(mlp_bng, mlp_bnb, inv_n, 2);
    mma_gemm_kernel<128, false, 3, 2, 1><<<gemmBlocks, TB>>>(p, nullptr, MP1, 0, mlp_b1, p2, n);
    stats_final_kernel<<<1, HID>>>(mlp_bng + HID, mlp_bnb + HID, inv_n, 3);
    mma_gemm_kernel<128, false, -1, 3, 1><<<gemmBlocks, TB>>>(p2, nullptr, MP2, 0, mlp_b2, p, n);

    // ---- CSR build ----
    zero_cnt_kernel<<<nodeBlocks, TB>>>(n);
    count_kernel<<<eBlocks, TB>>>(tgt, E);
    alloc_kernel<<<nodeBlocks, TB>>>(n);
    fill_kernel<<<eBlocks, TB>>>(src, tgt, E);

    // ---- SAGE layer 0 (inputs raw x) ----
    gather_agg_kernel<-1><<<warpNodeBlocks, TB>>>(x, agg, n);
    mma_gemm_kernel<128, true, 0, -1, 0><<<gemmBlocks, TB>>>(agg, x, WPL(0), WPR(0), sage_bl, h1, n);
    stats_final_kernel<<<1, HID>>>(sage_bng, sage_bnb, inv_n, 0);

    // ---- SAGE layer 1 (h1 raw, bn slot0 + relu fused into consumers) ----
    gather_agg_kernel<0><<<warpNodeBlocks, TB>>>(h1, agg, n);
    mma_gemm_kernel<128, true, 1, 0, 0><<<gemmBlocks, TB>>>(agg, h1, WPL(1), WPR(1), sage_bl + HID, h2, n);
    stats_final_kernel<<<1, HID>>>(sage_bng + HID, sage_bnb + HID, inv_n, 1);

    // ---- SAGE layer 2 (h2 raw, bn slot1 + relu fused; output raw) ----
    gather_agg_kernel<1><<<warpNodeBlocks, TB>>>(h2, agg, n);
    mma_gemm_kernel<128, true, -1, 1, 0><<<gemmBlocks, TB>>>(agg, h2, WPL(2), WPR(2), sage_bl + 2 * HID, h1, n);

    // ---- fusion + classifier + log_softmax ----
    classifier_kernel<<<nodeBlocks, TB>>>(h1, p, W_cls, b_cls, out, n);

    // ---- gate (gather form) ----
    gate_gather_kernel<<<warpNodeBlocks, TB>>>(temperature, out + (size_t)n * 40, n);
}

// round 12
// speedup vs baseline: 1.2997x; 1.2511x over previous
#include <cuda_runtime.h>
#include <cuda_bf16.h>
#include <math.h>

#define NMAX 100000
#define EMAX 1700000
#define HID 128
#define PROTO 64
#define BN_EPS 1e-5f
#define KC 32

typedef unsigned int uint32;

// ---------------- scratch (device globals: no allocation allowed) ----------------
__device__ float g_h1[NMAX * HID];
__device__ float g_h2[NMAX * HID];
__device__ float g_agg[NMAX * HID];
__device__ float g_p[NMAX * HID];
__device__ float g_p2[NMAX * HID];
__device__ float g_an[NMAX * PROTO];
__device__ int   g_cnt[NMAX];
__device__ int   g_off[NMAX + 1];
__device__ int   g_cur[NMAX];
__device__ int   g_csr[EMAX];
__device__ int   g_total;
__device__ float g_sum[4 * HID];
__device__ float g_sumsq[4 * HID];
__device__ float g_scaleS[4][HID];
__device__ float g_shiftS[4][HID];

// Weights in INTERLEAVED tf32 fragment layout: one float4 per "pair"
//   pair index: ((ktile*16 + ntile)*32 + lane)
//   float4 = { hi(reg0), hi(reg1), lo(reg0), lo(reg1) }
#define WPL(L) ((L) * 8192)
#define WPR(L) (24576 + (L) * 8192)
#define MP0 49152
#define MP1 53248
#define MP2 61440
#define NPAIRS 69632
__device__ float g_wf[NPAIRS * 4];

// ---------------- tf32 + cache-hint helpers ----------------
__device__ __forceinline__ uint32 cvt_tf32(float x) {
    uint32 r;
    asm("cvt.rna.tf32.f32 %0, %1;" : "=r"(r) : "f"(x));
    return r;
}
__device__ __forceinline__ void split_tf32(float x, float& hi, float& lo) {
    uint32 h = cvt_tf32(x);
    hi = __uint_as_float(h);
    lo = __uint_as_float(cvt_tf32(x - hi));
}
__device__ __forceinline__ void mma_tf32(float* c,
                                         uint32 a0, uint32 a1, uint32 a2, uint32 a3,
                                         uint32 b0, uint32 b1) {
    asm volatile("mma.sync.aligned.m16n8k8.row.col.f32.tf32.tf32.f32 "
                 "{%0,%1,%2,%3}, {%4,%5,%6,%7}, {%8,%9}, {%0,%1,%2,%3};"
                 : "+f"(c[0]), "+f"(c[1]), "+f"(c[2]), "+f"(c[3])
                 : "r"(a0), "r"(a1), "r"(a2), "r"(a3), "r"(b0), "r"(b1));
}
__device__ __forceinline__ float4 ldg_ef4(const float* p) {
    float4 v;
    asm("ld.global.nc.L1::evict_first.v4.f32 {%0,%1,%2,%3}, [%4];"
        : "=f"(v.x), "=f"(v.y), "=f"(v.z), "=f"(v.w) : "l"(p));
    return v;
}
__device__ __forceinline__ float4 ldg_el4(const float* p) {
    float4 v;
    asm("ld.global.nc.L1::evict_last.v4.f32 {%0,%1,%2,%3}, [%4];"
        : "=f"(v.x), "=f"(v.y), "=f"(v.z), "=f"(v.w) : "l"(p));
    return v;
}

// ---------------- init ----------------
__global__ void init_kernel() {
    int v = blockIdx.x * blockDim.x + threadIdx.x;
    if (v < 4 * HID) { g_sum[v] = 0.f; g_sumsq[v] = 0.f; }
    if (v == 0) g_total = 0;
}

__global__ void zero_cnt_kernel(int n) {
    int v = blockIdx.x * blockDim.x + threadIdx.x;
    if (v < n) g_cnt[v] = 0;
}
__global__ void count_kernel(const int* __restrict__ tgt, int E) {
    int e = blockIdx.x * blockDim.x + threadIdx.x;
    if (e < E) atomicAdd(&g_cnt[tgt[e]], 1);
}

// ---------------- CSR offset allocation (unordered block bases) ----------------
__global__ void alloc_kernel(int n) {
    __shared__ int wsums[8];
    __shared__ int base_s;
    int tid = threadIdx.x, lane = tid & 31, wid = tid >> 5;
    int i = blockIdx.x * 256 + tid;
    int v = (i < n) ? g_cnt[i] : 0;
    int s = v;
#pragma unroll
    for (int d = 1; d < 32; d <<= 1) {
        int t = __shfl_up_sync(0xFFFFFFFFu, s, d);
        if (lane >= d) s += t;
    }
    if (lane == 31) wsums[wid] = s;
    __syncthreads();
    if (tid == 0) {
        int run = 0;
#pragma unroll
        for (int w8 = 0; w8 < 8; w8++) { int t = wsums[w8]; wsums[w8] = run; run += t; }
        base_s = atomicAdd(&g_total, run);
    }
    __syncthreads();
    int excl = base_s + wsums[wid] + s - v;
    if (i < n) { g_off[i] = excl; g_cur[i] = excl; }
}

__global__ void fill_kernel(const int* __restrict__ src, const int* __restrict__ tgt, int E) {
    int e = blockIdx.x * blockDim.x + threadIdx.x;
    if (e >= E) return;
    int t = tgt[e];
    int pos = atomicAdd(&g_cur[t], 1);
    g_csr[pos] = src[e];
}

// ---------------- weight prep: transpose + split into interleaved fragment float4 ----------------
__global__ void prep_w_kernel(const float* __restrict__ sWl, const float* __restrict__ sWr,
                              const float* __restrict__ m0, const float* __restrict__ m1,
                              const float* __restrict__ m2) {
    int i = blockIdx.x * blockDim.x + threadIdx.x;
    if (i >= NPAIRS) return;
    int off, K;
    const float* mat;
    if (i < 24576)        { int L = i / 8192;           off = L * 8192;           mat = sWl + L * 16384; K = 128; }
    else if (i < 49152)   { int L = (i - 24576) / 8192; off = 24576 + L * 8192;   mat = sWr + L * 16384; K = 128; }
    else if (i < 53248)   { off = MP0; mat = m0; K = 64; }
    else if (i < 61440)   { off = MP1; mat = m1; K = 128; }
    else                  { off = MP2; mat = m2; K = 128; }
    int li   = i - off;
    int lane = li & 31;
    int nt   = (li >> 5) & 15;
    int kt   = li >> 9;
    int g4 = lane >> 2, t4 = lane & 3;
    int c = nt * 8 + g4;
    int k = kt * 8 + t4;
    float v0 = mat[c * K + k];
    float v1 = mat[c * K + k + 4];
    float h0, l0, h1, l1;
    split_tf32(v0, h0, l0);
    split_tf32(v1, h1, l1);
    *(float4*)&g_wf[(size_t)i * 4] = make_float4(h0, h1, l0, l1);
}

// ---------------- gather aggregation (segment mean), warp per node ----------------
template<int SLOT>
__global__ __launch_bounds__(256) void gather_agg_kernel(const float* __restrict__ h,
                                                         float* __restrict__ agg, int n) {
    int lane = threadIdx.x & 31;
    int v = blockIdx.x * 8 + (threadIdx.x >> 5);
    if (v >= n) return;
    int d0 = g_off[v];
    int c = g_cnt[v];
    int d1 = d0 + c;
    float4 sc, sh;
    if (SLOT >= 0) {
        sc = *(const float4*)&g_scaleS[SLOT][lane * 4];
        sh = *(const float4*)&g_shiftS[SLOT][lane * 4];
    }
    float4 acc = make_float4(0.f, 0.f, 0.f, 0.f);
    for (int j0 = d0; j0 < d1; j0 += 32) {
        int m = d1 - j0; if (m > 32) m = 32;
        int ul = (j0 + lane < d1) ? g_csr[j0 + lane] : 0;
        for (int t = 0; t < m; t++) {
            int u = __shfl_sync(0xFFFFFFFFu, ul, t);
            float4 x = *(const float4*)(h + (size_t)u * HID + lane * 4);
            if (SLOT >= 0) {
                x.x = fmaxf(x.x * sc.x + sh.x, 0.f);
                x.y = fmaxf(x.y * sc.y + sh.y, 0.f);
                x.z = fmaxf(x.z * sc.z + sh.z, 0.f);
                x.w = fmaxf(x.w * sc.w + sh.w, 0.f);
            }
            acc.x += x.x; acc.y += x.y; acc.z += x.z; acc.w += x.w;
        }
    }
    float inv = 1.0f / (float)(c > 0 ? c : 1);
    acc.x *= inv; acc.y *= inv; acc.z *= inv; acc.w *= inv;
    *(float4*)(agg + (size_t)v * HID + lane * 4) = acc;
}

// ---------------- gate branch ----------------
__global__ void normalize_alpha_kernel(const float* __restrict__ alpha, int n) {
    int v = blockIdx.x * blockDim.x + threadIdx.x;
    if (v >= n) return;
    const float4* a = (const float4*)(alpha + (size_t)v * PROTO);
    float4 vals[16];
    float ss = 0.f;
#pragma unroll
    for (int i = 0; i < 16; i++) {
        vals[i] = a[i];
        ss += vals[i].x * vals[i].x + vals[i].y * vals[i].y +
              vals[i].z * vals[i].z + vals[i].w * vals[i].w;
    }
    float inv = 1.0f / fmaxf(sqrtf(ss), 1e-12f);
    float4* o = (float4*)(g_an + (size_t)v * PROTO);
#pragma unroll
    for (int i = 0; i < 16; i++) {
        float4 t = vals[i];
        t.x *= inv; t.y *= inv; t.z *= inv; t.w *= inv;
        o[i] = t;
    }
}

__global__ __launch_bounds__(256) void gate_gather_kernel(const float* __restrict__ temp,
                                                          float* __restrict__ out, int n) {
    int lane = threadIdx.x & 31;
    int v = blockIdx.x * 8 + (threadIdx.x >> 5);
    if (v >= n) return;
    int d0 = g_off[v];
    int c = g_cnt[v];
    int d1 = d0 + c;
    float2 acc = make_float2(0.f, 0.f);
    for (int j0 = d0; j0 < d1; j0 += 32) {
        int m = d1 - j0; if (m > 32) m = 32;
        int ul = (j0 + lane < d1) ? g_csr[j0 + lane] : 0;
        for (int t = 0; t < m; t++) {
            int u = __shfl_sync(0xFFFFFFFFu, ul, t);
            float2 x = *(const float2*)(g_an + (size_t)u * PROTO + lane * 2);
            acc.x += x.x; acc.y += x.y;
        }
    }
    float2 av = *(const float2*)(g_an + (size_t)v * PROTO + lane * 2);
    float d = acc.x * av.x + acc.y * av.y;
#pragma unroll
    for (int s = 16; s > 0; s >>= 1) d += __shfl_down_sync(0xFFFFFFFFu, d, s);
    if (lane == 0) {
        float tv = __ldg(temp);
        float m = (1.0f + d) / (float)(c + 1);
        out[v] = 1.0f / (1.0f + expf(-tv * m));
    }
}

// ---------------- 3xTF32 tensor-core GEMM v6: warp m32n32, 64-row block, high occ + B reuse ----------------
// block 256 thr = 8 warps: wm = w&1 (2 m-groups of 32 rows), wn = w>>1 (4 n-groups of 32 cols).
// Each B fragment (LDG.128) feeds 6 mmas (3 terms x 2 m16 tiles).
#define ASZ6 2304
template<int K, bool DUAL, int STATS, int TRS, int TRA>
__global__ __launch_bounds__(256, 3) void mma_gemm_kernel(
    const float* __restrict__ A1, const float* __restrict__ A2,
    int w1p, int w2p,
    const float* __restrict__ bias, float* __restrict__ C, int n)
{
    __shared__ float As[2 * ASZ6];
    __shared__ float ssum[HID], ssq[HID];

    const int tid  = threadIdx.x;
    const int lane = tid & 31;
    const int w    = tid >> 5;
    const int row0 = blockIdx.x * 64;
    const int mt   = (w & 1) * 32;     // m16 tiles at mt, mt+16
    const int wn   = w >> 1;           // 0..3
    const int nb   = wn * 32;
    const int t4 = lane & 3;
    const int g4 = lane >> 2;

    if (STATS >= 0 && tid < HID) { ssum[tid] = 0.f; ssq[tid] = 0.f; }

    float acc[2][4][4];
#pragma unroll
    for (int j = 0; j < 4; j++) {
        int c0 = nb + j * 8 + 2 * t4;
        float b0 = bias[c0], b1 = bias[c0 + 1];
#pragma unroll
        for (int m2 = 0; m2 < 2; m2++) {
            acc[m2][j][0] = b0; acc[m2][j][1] = b1; acc[m2][j][2] = b0; acc[m2][j][3] = b1;
        }
    }

    constexpr int NCH = K / KC;
    constexpr int TOT = DUAL ? 2 * NCH : NCH;

    const int ar0 = tid >> 3;            // row 0..31
    const int akq = tid & 7;             // k-quad 0..7
    const int ar1 = ar0 + 32;
    const int gr0 = row0 + ar0, gr1 = row0 + ar1;

    auto xform = [&](float4& v, int cb) {
        if (TRS >= 0) {
            float4 sc = *(const float4*)&g_scaleS[TRS][cb];
            float4 sh = *(const float4*)&g_shiftS[TRS][cb];
            v.x = v.x * sc.x + sh.x; v.y = v.y * sc.y + sh.y;
            v.z = v.z * sc.z + sh.z; v.w = v.w * sc.w + sh.w;
            if (TRA == 0) {
                v.x = fmaxf(v.x, 0.f); v.y = fmaxf(v.y, 0.f);
                v.z = fmaxf(v.z, 0.f); v.w = fmaxf(v.w, 0.f);
            } else {
                v.x = 1.f / (1.f + expf(-v.x)); v.y = 1.f / (1.f + expf(-v.y));
                v.z = 1.f / (1.f + expf(-v.z)); v.w = 1.f / (1.f + expf(-v.w));
            }
        }
    };

    auto loadA = [&](int ch, float4& p0, float4& p1) {
        bool isA2 = (DUAL && ch >= NCH);
        const float* Ap = isA2 ? A2 : A1;
        int k0 = (ch % NCH) * KC;
        bool tr = DUAL ? isA2 : true;
        p0 = (gr0 < n) ? ldg_ef4(Ap + (size_t)gr0 * K + k0 + akq * 4) : make_float4(0, 0, 0, 0);
        p1 = (gr1 < n) ? ldg_ef4(Ap + (size_t)gr1 * K + k0 + akq * 4) : make_float4(0, 0, 0, 0);
        if (tr) { if (gr0 < n) xform(p0, k0 + akq * 4); if (gr1 < n) xform(p1, k0 + akq * 4); }
    };
    auto storeA = [&](int buf, const float4& p0, const float4& p1) {
        *(float4*)&As[buf * ASZ6 + ar0 * 36 + akq * 4] = p0;
        *(float4*)&As[buf * ASZ6 + ar1 * 36 + akq * 4] = p1;
    };

    // ---- prologue: chunk 0 ----
    {
        float4 p0, p1;
        loadA(0, p0, p1);
        storeA(0, p0, p1);
    }
    __syncthreads();

#pragma unroll 1
    for (int ch = 0; ch < TOT; ch++) {
        const int cur = ch & 1, nxt = cur ^ 1;
        const bool more = (ch + 1 < TOT);
        float4 p0, p1;
        if (more) loadA(ch + 1, p0, p1);
        // ---- math on cur ----
        {
            const float* Ac = As + cur * ASZ6;
            const int wbase = ((DUAL && ch >= NCH) ? w2p : w1p) + (ch % NCH) * 2048;
#pragma unroll
            for (int kt = 0; kt < 4; kt++) {
                uint32 ah[2][4], al[2][4];
#pragma unroll
                for (int m2 = 0; m2 < 2; m2++) {
                    int base = (mt + m2 * 16 + g4) * 36 + kt * 8 + t4;
                    float ra0 = Ac[base], ra1 = Ac[base + 8 * 36];
                    float ra2 = Ac[base + 4], ra3 = Ac[base + 8 * 36 + 4];
                    float h0, l0, h1, l1, h2, l2, h3, l3;
                    split_tf32(ra0, h0, l0); split_tf32(ra1, h1, l1);
                    split_tf32(ra2, h2, l2); split_tf32(ra3, h3, l3);
                    ah[m2][0] = __float_as_uint(h0); ah[m2][1] = __float_as_uint(h1);
                    ah[m2][2] = __float_as_uint(h2); ah[m2][3] = __float_as_uint(h3);
                    al[m2][0] = __float_as_uint(l0); al[m2][1] = __float_as_uint(l1);
                    al[m2][2] = __float_as_uint(l2); al[m2][3] = __float_as_uint(l3);
                }
#pragma unroll
                for (int j = 0; j < 4; j++) {
                    int jg = wn * 4 + j;
                    int pidx = wbase + (kt * 16 + jg) * 32 + lane;
                    float4 bf = ldg_el4(g_wf + (size_t)pidx * 4);
                    uint32 bh0 = __float_as_uint(bf.x), bh1 = __float_as_uint(bf.y);
                    uint32 bl0 = __float_as_uint(bf.z), bl1 = __float_as_uint(bf.w);
#pragma unroll
                    for (int m2 = 0; m2 < 2; m2++) {
                        mma_tf32(acc[m2][j], ah[m2][0], ah[m2][1], ah[m2][2], ah[m2][3], bh0, bh1);
                        mma_tf32(acc[m2][j], ah[m2][0], ah[m2][1], ah[m2][2], ah[m2][3], bl0, bl1);
                        mma_tf32(acc[m2][j], al[m2][0], al[m2][1], al[m2][2], al[m2][3], bh0, bh1);
                    }
                }
            }
        }
        if (more) storeA(nxt, p0, p1);
        __syncthreads();
    }

    // ---- epilogue: store + fused stats ----
#pragma unroll
    for (int j = 0; j < 4; j++) {
        int c0 = nb + j * 8 + 2 * t4;
        float s0 = 0.f, s1 = 0.f, q0 = 0.f, q1 = 0.f;
#pragma unroll
        for (int m2 = 0; m2 < 2; m2++) {
            int r0 = row0 + mt + m2 * 16 + g4;
            int r1 = r0 + 8;
            if (r0 < n) {
                *(float2*)(C + (size_t)r0 * HID + c0) = make_float2(acc[m2][j][0], acc[m2][j][1]);
                s0 += acc[m2][j][0]; s1 += acc[m2][j][1];
                q0 += acc[m2][j][0] * acc[m2][j][0]; q1 += acc[m2][j][1] * acc[m2][j][1];
            }
            if (r1 < n) {
                *(float2*)(C + (size_t)r1 * HID + c0) = make_float2(acc[m2][j][2], acc[m2][j][3]);
                s0 += acc[m2][j][2]; s1 += acc[m2][j][3];
                q0 += acc[m2][j][2] * acc[m2][j][2]; q1 += acc[m2][j][3] * acc[m2][j][3];
            }
        }
        if (STATS >= 0) {
            atomicAdd(&ssum[c0], s0); atomicAdd(&ssum[c0 + 1], s1);
            atomicAdd(&ssq[c0], q0);  atomicAdd(&ssq[c0 + 1], q1);
        }
    }
    if (STATS >= 0) {
        __syncthreads();
        if (tid < HID) {
            atomicAdd(&g_sum[STATS * HID + tid], ssum[tid]);
            atomicAdd(&g_sumsq[STATS * HID + tid], ssq[tid]);
        }
    }
}

// ---------------- BN finalize ----------------
__global__ void stats_final_kernel(const float* __restrict__ gamma, const float* __restrict__ beta,
                                   float inv_n, int slot) {
    int c = threadIdx.x;
    float mu = g_sum[slot * HID + c] * inv_n;
    float var = g_sumsq[slot * HID + c] * inv_n - mu * mu;
    float sc = gamma[c] * rsqrtf(var + BN_EPS);
    g_scaleS[slot][c] = sc;
    g_shiftS[slot][c] = beta[c] - mu * sc;
}

// ---------------- classifier + log_softmax ----------------
__global__ __launch_bounds__(256) void classifier_kernel(
    const float* __restrict__ hg, const float* __restrict__ hp,
    const float* __restrict__ Wc, const float* __restrict__ bc,
    float* __restrict__ out, int n)
{
    __shared__ float wcs[40 * 256];
    __shared__ float bcs[40];
    int tid = threadIdx.x;
    for (int i = tid; i < 40 * 256; i += 256) wcs[i] = Wc[i];
    if (tid < 40) bcs[tid] = bc[tid];
    __syncthreads();
    int r = blockIdx.x * 256 + tid;
    if (r >= n) return;

    float acc[40];
#pragma unroll
    for (int o = 0; o < 40; o++) acc[o] = bcs[o];

    for (int half = 0; half < 2; half++) {
        const float* src = half ? hp : hg;
        for (int k4 = 0; k4 < 32; k4++) {
            float4 z = *(const float4*)(src + (size_t)r * HID + k4 * 4);
            z.x = fmaxf(z.x, 0.f); z.y = fmaxf(z.y, 0.f);
            z.z = fmaxf(z.z, 0.f); z.w = fmaxf(z.w, 0.f);
            int kb = half * 128 + k4 * 4;
#pragma unroll
            for (int o = 0; o < 40; o++) {
                float4 wv = *(float4*)&wcs[o * 256 + kb];
                acc[o] += z.x * wv.x + z.y * wv.y + z.z * wv.z + z.w * wv.w;
            }
        }
    }
    float m = acc[0];
#pragma unroll
    for (int o = 1; o < 40; o++) m = fmaxf(m, acc[o]);
    float s = 0.f;
#pragma unroll
    for (int o = 0; o < 40; o++) s += expf(acc[o] - m);
    float lse = m + logf(s);
    float* op = out + (size_t)r * 40;
#pragma unroll
    for (int o = 0; o < 40; o++) op[o] = acc[o] - lse;
}

// ---------------- streams (created at program init; no device allocation) ----------------
struct StreamInit {
    cudaStream_t s1; cudaEvent_t evF, evJ; bool ok;
    StreamInit() {
        ok = (cudaStreamCreateWithFlags(&s1, cudaStreamNonBlocking) == cudaSuccess) &&
             (cudaEventCreateWithFlags(&evF, cudaEventDisableTiming) == cudaSuccess) &&
             (cudaEventCreateWithFlags(&evJ, cudaEventDisableTiming) == cudaSuccess);
    }
};
static StreamInit g_si;

// ---------------- launcher ----------------
extern "C" void kernel_launch(void* const* d_in, const int* in_sizes, int n_in,
                              void* d_out, int out_size) {
    const float* x           = (const float*)d_in[0];
    const float* alpha       = (const float*)d_in[1];
    const int*   ei          = (const int*)d_in[2];
    const float* sage_Wl     = (const float*)d_in[3];
    const float* sage_bl     = (const float*)d_in[4];
    const float* sage_Wr     = (const float*)d_in[5];
    const float* sage_bng    = (const float*)d_in[6];
    const float* sage_bnb    = (const float*)d_in[7];
    const float* mlp_W0      = (const float*)d_in[8];
    const float* mlp_b0      = (const float*)d_in[9];
    const float* mlp_W1      = (const float*)d_in[10];
    const float* mlp_b1      = (const float*)d_in[11];
    const float* mlp_W2      = (const float*)d_in[12];
    const float* mlp_b2      = (const float*)d_in[13];
    const float* mlp_bng     = (const float*)d_in[14];
    const float* mlp_bnb     = (const float*)d_in[15];
    const float* W_cls       = (const float*)d_in[16];
    const float* b_cls       = (const float*)d_in[17];
    const float* temperature = (const float*)d_in[18];

    int n = in_sizes[0] / HID;
    int E = in_sizes[2] / 2;
    const int* src = ei;
    const int* tgt = ei + E;
    float* out = (float*)d_out;

    float *h1, *h2, *agg, *p, *p2;
    cudaGetSymbolAddress((void**)&h1,  g_h1);
    cudaGetSymbolAddress((void**)&h2,  g_h2);
    cudaGetSymbolAddress((void**)&agg, g_agg);
    cudaGetSymbolAddress((void**)&p,   g_p);
    cudaGetSymbolAddress((void**)&p2,  g_p2);

    const int TB = 256;
    int nodeBlocks = (n + TB - 1) / TB;
    int warpNodeBlocks = (n + 7) / 8;
    int gemmBlocks = (n + 63) / 64;
    float inv_n = 1.0f / (float)n;
    int eBlocks = (E + TB - 1) / TB;

    bool fork = g_si.ok;
    cudaStream_t sp = fork ? g_si.s1 : (cudaStream_t)0;  // proto-branch stream

    // ---- shared prologue (main stream) ----
    init_kernel<<<2, TB>>>();
    prep_w_kernel<<<(NPAIRS + TB - 1) / TB, TB>>>(sage_Wl, sage_Wr, mlp_W0, mlp_W1, mlp_W2);

    if (fork) {
        cudaEventRecord(g_si.evF, 0);
        cudaStreamWaitEvent(sp, g_si.evF, 0);
    }

    // ---- proto branch (side stream) ----
    normalize_alpha_kernel<<<nodeBlocks, TB, 0, sp>>>(alpha, n);
    mma_gemm_kernel<64, false, 2, -1, 0><<<gemmBlocks, TB, 0, sp>>>(alpha, nullptr, MP0, 0, mlp_b0, p, n);
    stats_final_kernel<<<1, HID, 0, sp>>>(mlp_bng, mlp_bnb, inv_n, 2);
    mma_gemm_kernel<128, false, 3, 2, 1><<<gemmBlocks, TB, 0, sp>>>(p, nullptr, MP1, 0, mlp_b1, p2, n);
    stats_final_kernel<<<1, HID, 0, sp>>>(mlp_bng + HID, mlp_bnb + HID, inv_n, 3);
    mma_gemm_kernel<128, false, -1, 3, 1><<<gemmBlocks, TB, 0, sp>>>(p2, nullptr, MP2, 0, mlp_b2, p, n);
    if (fork) cudaEventRecord(g_si.evJ, sp);

    // ---- CSR build + SAGE chain (main stream, concurrent with proto) ----
    zero_cnt_kernel<<<nodeBlocks, TB>>>(n);
    count_kernel<<<eBlocks, TB>>>(tgt, E);
    alloc_kernel<<<nodeBlocks, TB>>>(n);
    fill_kernel<<<eBlocks, TB>>>(src, tgt, E);

    gather_agg_kernel<-1><<<warpNodeBlocks, TB>>>(x, agg, n);
    mma_gemm_kernel<128, true, 0, -1, 0><<<gemmBlocks, TB>>>(agg, x, WPL(0), WPR(0), sage_bl, h1, n);
    stats_final_kernel<<<1, HID>>>(sage_bng, sage_bnb, inv_n, 0);

    gather_agg_kernel<0><<<warpNodeBlocks, TB>>>(h1, agg, n);
    mma_gemm_kernel<128, true, 1, 0, 0><<<gemmBlocks, TB>>>(agg, h1, WPL(1), WPR(1), sage_bl + HID, h2, n);
    stats_final_kernel<<<1, HID>>>(sage_bng + HID, sage_bnb + HID, inv_n, 1);

    gather_agg_kernel<1><<<warpNodeBlocks, TB>>>(h2, agg, n);
    mma_gemm_kernel<128, true, -1, 1, 0><<<gemmBlocks, TB>>>(agg, h2, WPL(2), WPR(2), sage_bl + 2 * HID, h1, n);

    // ---- join proto branch, then fusion + classifier + gate ----
    if (fork) cudaStreamWaitEvent(0, g_si.evJ, 0);
    classifier_kernel<<<nodeBlocks, TB>>>(h1, p, W_cls, b_cls, out, n);
    gate_gather_kernel<<<warpNodeBlocks, TB>>>(temperature, out + (size_t)n * 40, n);
}